// round 3
// baseline (speedup 1.0000x reference)
#include <cuda_runtime.h>
#include <math.h>
#include <stdint.h>

// ---------------- problem constants ----------------
#define B_SZ   4096
#define LATENT 512
#define D_     6
#define M_     16
#define K_     12      // knots
#define NB_    16
#define R_     128
#define HID_   256
#define KIN    518     // LATENT + D
#define NP_    368     // M*(1+NB+D)
#define NK_    192     // M*K

// output layout (tuple flattened in order)
#define OFF_LOGITS 0ull
#define OFF_MU     65536ull
#define OFF_SIG    (65536ull + 50331648ull)                 // 50397184
#define OFF_MASK   (50397184ull + 50331648ull)              // 100728832
#define OFF_BW     (100728832ull + 786432ull)               // 101515264

// ---------------- scratch (no allocs allowed) ----------------
__device__ float g_X [B_SZ * KIN];   // concat(latent, intent)
__device__ float g_H [B_SZ * HID_];  // pre-LN hidden
__device__ float g_A [B_SZ * HID_];  // elu(LN(h))
__device__ float g_S [B_SZ * HID_];  // situation
__device__ float g_P [B_SZ * NP_];   // raw head
__device__ float g_Kc[B_SZ * NK_];   // knot logits

// ---------------- kernel 1: build concat input ----------------
__global__ void build_x_kernel(const float* __restrict__ ls,
                               const float* __restrict__ intent) {
    int idx = blockIdx.x * blockDim.x + threadIdx.x;
    if (idx >= B_SZ * KIN) return;
    int b = idx / KIN;
    int k = idx - b * KIN;
    g_X[idx] = (k < LATENT) ? ls[b * LATENT + k] : intent[b * D_ + (k - LATENT)];
}

// ---------------- generic fp32 tiled GEMM: C = A[BxK] @ W[KxN] + bias ----
// BM=64, BN=64, KT=16, 256 threads, 4x4 thread tile.
__global__ void gemm64_kernel(const float* __restrict__ A,
                              const float* __restrict__ W,
                              const float* __restrict__ bias,
                              float* __restrict__ C,
                              int K, int N) {
    __shared__ float As[16][64];
    __shared__ float Ws[16][64];

    const int bm = blockIdx.y * 64;
    const int bn = blockIdx.x * 64;
    const int tid = threadIdx.x;
    const int tx = tid & 15;       // col group
    const int ty = tid >> 4;       // row group

    float acc[4][4];
#pragma unroll
    for (int i = 0; i < 4; i++)
#pragma unroll
        for (int j = 0; j < 4; j++) acc[i][j] = 0.f;

    for (int k0 = 0; k0 < K; k0 += 16) {
        // A tile: 64 rows x 16 k, stored k-major
#pragma unroll
        for (int i = 0; i < 4; i++) {
            int idx = tid + i * 256;
            int r  = idx >> 4;
            int kc = idx & 15;
            float v = 0.f;
            if (k0 + kc < K) v = A[(size_t)(bm + r) * K + (k0 + kc)];
            As[kc][r] = v;
        }
        // W tile: 16 k x 64 n
#pragma unroll
        for (int i = 0; i < 4; i++) {
            int idx = tid + i * 256;
            int kr = idx >> 6;
            int c  = idx & 63;
            float v = 0.f;
            if ((k0 + kr) < K && (bn + c) < N) v = W[(size_t)(k0 + kr) * N + (bn + c)];
            Ws[kr][c] = v;
        }
        __syncthreads();

#pragma unroll
        for (int k = 0; k < 16; k++) {
            float4 a4 = *(const float4*)&As[k][ty * 4];
            float4 w4 = *(const float4*)&Ws[k][tx * 4];
            acc[0][0] += a4.x * w4.x; acc[0][1] += a4.x * w4.y; acc[0][2] += a4.x * w4.z; acc[0][3] += a4.x * w4.w;
            acc[1][0] += a4.y * w4.x; acc[1][1] += a4.y * w4.y; acc[1][2] += a4.y * w4.z; acc[1][3] += a4.y * w4.w;
            acc[2][0] += a4.z * w4.x; acc[2][1] += a4.z * w4.y; acc[2][2] += a4.z * w4.z; acc[2][3] += a4.z * w4.w;
            acc[3][0] += a4.w * w4.x; acc[3][1] += a4.w * w4.y; acc[3][2] += a4.w * w4.z; acc[3][3] += a4.w * w4.w;
        }
        __syncthreads();
    }

#pragma unroll
    for (int i = 0; i < 4; i++) {
        int r = bm + ty * 4 + i;
#pragma unroll
        for (int j = 0; j < 4; j++) {
            int c = bn + tx * 4 + j;
            if (c < N) C[(size_t)r * N + c] = acc[i][j] + bias[c];
        }
    }
}

// ---------------- LayerNorm + elu ----------------
__global__ void ln_elu_kernel(const float* __restrict__ g,
                              const float* __restrict__ bb) {
    const int b = blockIdx.x;
    const int t = threadIdx.x;   // 256
    float x = g_H[(size_t)b * HID_ + t];
    float v = x, v2 = x * x;
#pragma unroll
    for (int o = 16; o > 0; o >>= 1) {
        v  += __shfl_xor_sync(0xffffffffu, v,  o);
        v2 += __shfl_xor_sync(0xffffffffu, v2, o);
    }
    __shared__ float s1[8], s2[8];
    int wid = t >> 5, lane = t & 31;
    if (lane == 0) { s1[wid] = v; s2[wid] = v2; }
    __syncthreads();
    float tot = 0.f, tot2 = 0.f;
#pragma unroll
    for (int i = 0; i < 8; i++) { tot += s1[i]; tot2 += s2[i]; }
    float mu  = tot * (1.f / 256.f);
    float var = tot2 * (1.f / 256.f) - mu * mu;
    float y = (x - mu) * rsqrtf(var + 1e-5f) * g[t] + bb[t];
    g_A[(size_t)b * HID_ + t] = (y > 0.f) ? y : expm1f(y);
}

// ---------------- finalize: heads + knots + spline + all outputs ------
__global__ void finalize_kernel(const float* __restrict__ prev_vel,
                                const float* __restrict__ intent,
                                const float* __restrict__ basis,
                                float* __restrict__ out) {
    const int b = blockIdx.x;
    const int t = threadIdx.x;   // 256

    __shared__ float basis_s[NB_ * K_ * D_];   // 1152
    __shared__ float pv_s[D_], it_s[D_];
    __shared__ float bw_s[NB_];
    __shared__ float sig_s[D_];
    __shared__ float msk_s[K_];
    __shared__ float kna[K_ * D_];
    __shared__ float knb[K_ * D_];
    __shared__ int   cidx[K_];
    __shared__ int   cnt_s;

    for (int i = t; i < NB_ * K_ * D_; i += 256) basis_s[i] = basis[i];
    if (t == 0) {
        float n2 = 0.f, pv[D_];
#pragma unroll
        for (int d = 0; d < D_; d++) { pv[d] = prev_vel[(size_t)b * D_ + d]; n2 += pv[d] * pv[d]; }
        float inv = 1.f / (sqrtf(n2) + 1e-6f);
#pragma unroll
        for (int d = 0; d < D_; d++) {
            pv_s[d] = pv[d] * inv;
            it_s[d] = intent[(size_t)b * D_ + d];
        }
    }
    __syncthreads();

    for (int m = 0; m < M_; m++) {
        // ---- heads ----
        if (t < 23) {
            float r = g_P[(size_t)b * NP_ + m * 23 + t];
            if (t == 0) {
                out[OFF_LOGITS + (size_t)b * M_ + m] = r;
            } else if (t <= NB_) {
                float v = tanhf(r);
                bw_s[t - 1] = v;
                out[OFF_BW + ((size_t)(b * M_ + m)) * NB_ + (t - 1)] = v;
            } else {
                sig_s[t - 1 - NB_] = expf(r) + 0.1f;
            }
        }
        if (t >= 32 && t < 32 + K_) {
            int k = t - 32;
            float kv = g_Kc[(size_t)b * NK_ + m * K_ + k];
            float sg = 1.f / (1.f + expf(-kv));
            float mv = (k == 0 || k == K_ - 1) ? 1.0f : sg;
            msk_s[k] = mv;
            out[OFF_MASK + ((size_t)(b * M_ + m)) * K_ + k] = mv;
        }
        __syncthreads();

        // ---- knots = bw @ basis ----
        if (t < K_ * D_) {
            float acc = 0.f;
#pragma unroll
            for (int n = 0; n < NB_; n++) acc += bw_s[n] * basis_s[n * (K_ * D_) + t];
            kna[t] = acc;
        }
        __syncthreads();
        if (t < K_ * D_) knb[t] = kna[t] - kna[t % D_];   // subtract knot 0
        __syncthreads();

        // ---- knot 1 alignment, last knot shift, mask compaction ----
        if (t == 0) {
            float n2 = 0.f, fs[D_];
#pragma unroll
            for (int d = 0; d < D_; d++) { fs[d] = knb[D_ + d]; n2 += fs[d] * fs[d]; }
            float mag = sqrtf(n2);
            float invm = 1.f / (mag + 1e-6f);
            float al[D_]; float an2 = 0.f;
#pragma unroll
            for (int d = 0; d < D_; d++) {
                float fn = fs[d] * invm;
                al[d] = 0.8f * pv_s[d] + 0.2f * fn;
                an2 += al[d] * al[d];
            }
            float inva = 1.f / (sqrtf(an2) + 1e-6f);
#pragma unroll
            for (int d = 0; d < D_; d++) knb[D_ + d] = al[d] * inva * mag;
#pragma unroll
            for (int d = 0; d < D_; d++) knb[(K_ - 1) * D_ + d] += 0.5f * it_s[d];
            int c = 0;
#pragma unroll
            for (int k = 0; k < K_; k++) if (msk_s[k] > 0.5f) cidx[c++] = k;
            cnt_s = c;
        }
        __syncthreads();

        const int count = cnt_s;
        if (t < R_) {
            // Catmull-Rom on compacted knots
            float s  = (float)t * (1.0f / 127.0f);
            float xs = s * (float)(count - 1);
            int j = (int)floorf(xs);
            if (j > count - 2) j = count - 2;
            if (j < 0) j = 0;
            float u = xs - (float)j;
            float u2 = u * u, u3 = u2 * u;
            int i0 = cidx[(j - 1 > 0) ? j - 1 : 0];
            int i1 = cidx[j];
            int i2 = cidx[j + 1];
            int i3 = cidx[(j + 2 < count - 1) ? j + 2 : count - 1];
            size_t base = OFF_MU + (((size_t)(b * M_ + m) * R_ + t) * D_);
#pragma unroll
            for (int d = 0; d < D_; d++) {
                float p0 = knb[i0 * D_ + d];
                float p1 = knb[i1 * D_ + d];
                float p2 = knb[i2 * D_ + d];
                float p3 = knb[i3 * D_ + d];
                float val = 0.5f * (2.f * p1
                                    + (-p0 + p2) * u
                                    + (2.f * p0 - 5.f * p1 + 4.f * p2 - p3) * u2
                                    + (-p0 + 3.f * p1 - 3.f * p2 + p3) * u3);
                out[base + d] = val;
            }
        } else {
            int tt = t - R_;
            size_t base = OFF_SIG + (((size_t)(b * M_ + m) * R_ + tt) * D_);
#pragma unroll
            for (int d = 0; d < D_; d++) out[base + d] = sig_s[d];
        }
        __syncthreads();
    }
}

// ---------------- launcher ----------------
extern "C" void kernel_launch(void* const* d_in, const int* in_sizes, int n_in,
                              void* d_out, int out_size) {
    (void)in_sizes; (void)n_in; (void)out_size;
    const float* ls     = (const float*)d_in[0];
    const float* intent = (const float*)d_in[1];
    const float* pvel   = (const float*)d_in[2];
    const float* W1     = (const float*)d_in[3];
    const float* b1     = (const float*)d_in[4];
    const float* lng    = (const float*)d_in[5];
    const float* lnb    = (const float*)d_in[6];
    const float* W2     = (const float*)d_in[7];
    const float* b2     = (const float*)d_in[8];
    const float* Wp     = (const float*)d_in[9];
    const float* bp     = (const float*)d_in[10];
    const float* Wk     = (const float*)d_in[11];
    const float* bk     = (const float*)d_in[12];
    const float* basis  = (const float*)d_in[13];
    float* out = (float*)d_out;

    float *pX, *pH, *pA, *pS, *pP, *pK;
    cudaGetSymbolAddress((void**)&pX, g_X);
    cudaGetSymbolAddress((void**)&pH, g_H);
    cudaGetSymbolAddress((void**)&pA, g_A);
    cudaGetSymbolAddress((void**)&pS, g_S);
    cudaGetSymbolAddress((void**)&pP, g_P);
    cudaGetSymbolAddress((void**)&pK, g_Kc);

    // 1) concat input
    {
        int tot = B_SZ * KIN;
        build_x_kernel<<<(tot + 255) / 256, 256>>>(ls, intent);
    }
    // 2) H = X @ W1 + b1
    gemm64_kernel<<<dim3(HID_ / 64, B_SZ / 64), 256>>>(pX, W1, b1, pH, KIN, HID_);
    // 3) A = elu(LN(H))
    ln_elu_kernel<<<B_SZ, 256>>>(lng, lnb);
    // 4) S = A @ W2 + b2
    gemm64_kernel<<<dim3(HID_ / 64, B_SZ / 64), 256>>>(pA, W2, b2, pS, HID_, HID_);
    // 5) P = S @ Wp + bp   (N=368 -> 6 col tiles)
    gemm64_kernel<<<dim3((NP_ + 63) / 64, B_SZ / 64), 256>>>(pS, Wp, bp, pP, HID_, NP_);
    // 6) Kc = S @ Wk + bk  (N=192 -> 3 col tiles)
    gemm64_kernel<<<dim3(NK_ / 64, B_SZ / 64), 256>>>(pS, Wk, bk, pK, HID_, NK_);
    // 7) heads + knots + spline + all outputs
    finalize_kernel<<<B_SZ, 256>>>(pvel, intent, basis, out);
}